// round 7
// baseline (speedup 1.0000x reference)
#include <cuda_runtime.h>
#include <cstdint>

// x:   [B=2, 1, D=64, H=256, W=256] fp32
// out: [B=2, 16, D=64, H=256, W=256] fp32
//   even channel -> per-slice 2D sobel magnitude, odd channel -> x
//
// Block = 8 warps = 8 consecutive rows of one slice. Sobel computed in
// registers (warp-per-row, shuffle halos), sobel+x staged to SMEM (16KB),
// then 16 x cp.async.bulk S2G stores of 8KB contiguous per channel.

#define W 256
#define H 256
#define DD 64
#define NB 2
#define RB 8           // rows per block

__device__ __forceinline__ float fsqrt_approx(float a) {
    float r;
    asm("sqrt.approx.f32 %0, %1;" : "=f"(r) : "f"(a));
    return r;
}

__device__ __forceinline__ uint32_t smem_u32(const void* p) {
    uint32_t a;
    asm("{ .reg .u64 t; cvta.to.shared.u64 t, %1; cvt.u32.u64 %0, t; }"
        : "=r"(a) : "l"(p));
    return a;
}

__global__ __launch_bounds__(256) void sobel_cat_kernel(
    const float* __restrict__ x, float* __restrict__ out)
{
    __shared__ alignas(128) float s_sob[RB * W];   // 8KB
    __shared__ alignas(128) float s_x[RB * W];     // 8KB

    const int wid  = threadIdx.x >> 5;
    const int lane = threadIdx.x & 31;
    const int rg   = blockIdx.x & (H / RB - 1);    // row-group within slice
    const int bd   = blockIdx.x >> 5;              // b*D + d   (H/RB = 32)
    const int h    = (rg << 3) + wid;              // this warp's row
    const int w0   = lane << 2;                    // chunk0 at w0, chunk1 at w0+128

    const float* base = x + ((size_t)bd * H + h) * W + w0;

    float4 z = make_float4(0.f, 0.f, 0.f, 0.f);
    float4 t0 = z, t1 = z, b0 = z, b1 = z;
    float4 m0 = __ldg((const float4*)base);
    float4 m1 = __ldg((const float4*)(base + 128));
    if (h > 0) {
        t0 = __ldg((const float4*)(base - W));
        t1 = __ldg((const float4*)(base + 128 - W));
    }
    if (h < H - 1) {
        b0 = __ldg((const float4*)(base + W));
        b1 = __ldg((const float4*)(base + 128 + W));
    }

    const unsigned full = 0xFFFFFFFFu;
    float tl0, tr0, tl1, tr1, ml0, mr0, ml1, mr1, bl0, br0, bl1, br1;
#define HALO(v0, v1, l0, r0, l1, r1)                                   \
    {                                                                  \
        l0 = __shfl_up_sync(full, (v0).w, 1);                          \
        r0 = __shfl_down_sync(full, (v0).x, 1);                        \
        l1 = __shfl_up_sync(full, (v1).w, 1);                          \
        r1 = __shfl_down_sync(full, (v1).x, 1);                        \
        float _x0  = __shfl_sync(full, (v1).x, 0);                     \
        float _w31 = __shfl_sync(full, (v0).w, 31);                    \
        if (lane == 0)  { l0 = 0.f;  l1 = _w31; }                      \
        if (lane == 31) { r0 = _x0;  r1 = 0.f;  }                      \
    }
    HALO(t0, t1, tl0, tr0, tl1, tr1)
    HALO(m0, m1, ml0, mr0, ml1, mr1)
    HALO(b0, b1, bl0, br0, bl1, br1)
#undef HALO

    float4 s0, s1;
    {
        float T[6] = { tl0, t0.x, t0.y, t0.z, t0.w, tr0 };
        float M[6] = { ml0, m0.x, m0.y, m0.z, m0.w, mr0 };
        float Bt[6] = { bl0, b0.x, b0.y, b0.z, b0.w, br0 };
        float* s = reinterpret_cast<float*>(&s0);
#pragma unroll
        for (int i = 0; i < 4; i++) {
            float gx = (T[i+2] - T[i]) + 2.f*(M[i+2] - M[i]) + (Bt[i+2] - Bt[i]);
            float gy = (Bt[i] - T[i]) + 2.f*(Bt[i+1] - T[i+1]) + (Bt[i+2] - T[i+2]);
            s[i] = fsqrt_approx(gx*gx + gy*gy);
        }
    }
    {
        float T[6] = { tl1, t1.x, t1.y, t1.z, t1.w, tr1 };
        float M[6] = { ml1, m1.x, m1.y, m1.z, m1.w, mr1 };
        float Bt[6] = { bl1, b1.x, b1.y, b1.z, b1.w, br1 };
        float* s = reinterpret_cast<float*>(&s1);
#pragma unroll
        for (int i = 0; i < 4; i++) {
            float gx = (T[i+2] - T[i]) + 2.f*(M[i+2] - M[i]) + (Bt[i+2] - Bt[i]);
            float gy = (Bt[i] - T[i]) + 2.f*(Bt[i+1] - T[i+1]) + (Bt[i+2] - T[i+2]);
            s[i] = fsqrt_approx(gx*gx + gy*gy);
        }
    }

    // stage to smem
    *(float4*)(s_sob + wid * W + w0)       = s0;
    *(float4*)(s_sob + wid * W + w0 + 128) = s1;
    *(float4*)(s_x   + wid * W + w0)       = m0;
    *(float4*)(s_x   + wid * W + w0 + 128) = m1;

    __syncthreads();
    asm volatile("fence.proxy.async.shared::cta;" ::: "memory");

    if (threadIdx.x == 0) {
        const uint32_t a_sob = smem_u32(s_sob);
        const uint32_t a_x   = smem_u32(s_x);
        const int bb = bd >> 6;
        const int dd = bd & (DD - 1);
        const size_t cs = (size_t)DD * H * W;       // channel stride (elems)
        float* ob = out + (((size_t)bb * 16 * DD + dd) * H + (size_t)(rg << 3)) * W;
        const uint32_t bytes = RB * W * 4;          // 8192
#pragma unroll
        for (int c = 0; c < 8; c++) {
            asm volatile(
                "cp.async.bulk.global.shared::cta.bulk_group [%0], [%1], %2;"
                :: "l"(ob + (size_t)(2 * c) * cs), "r"(a_sob), "r"(bytes)
                : "memory");
            asm volatile(
                "cp.async.bulk.global.shared::cta.bulk_group [%0], [%1], %2;"
                :: "l"(ob + (size_t)(2 * c + 1) * cs), "r"(a_x), "r"(bytes)
                : "memory");
        }
        asm volatile("cp.async.bulk.commit_group;" ::: "memory");
        asm volatile("cp.async.bulk.wait_group 0;" ::: "memory");
    }
}

extern "C" void kernel_launch(void* const* d_in, const int* in_sizes, int n_in,
                              void* d_out, int out_size)
{
    const float* x = (const float*)d_in[0];
    float* out = (float*)d_out;

    // one block per 8-row group: NB*DD*(H/RB) = 4096 blocks
    const int blocks = NB * DD * (H / RB);
    sobel_cat_kernel<<<blocks, 256>>>(x, out);
}

// round 8
// speedup vs baseline: 1.0116x; 1.0116x over previous
#include <cuda_runtime.h>

// x:   [B=2, 1, D=64, H=256, W=256] fp32
// out: [B=2, 16, D=64, H=256, W=256] fp32
//   even channel -> per-slice 2D sobel magnitude, odd channel -> x
//
// R4 structure (best): warp = one full 256-px row, lane owns two float4
// chunks (w=4l, w=4l+128), halos via shuffle, sqrt.approx, 32 coalesced
// STG.128 per thread. ONLY change vs R4: default-policy stores (no .cs)
// to let L2 batch dirty-line writeback.

#define W 256
#define H 256
#define DD 64
#define NB 2

__device__ __forceinline__ float fsqrt_approx(float a) {
    float r;
    asm("sqrt.approx.f32 %0, %1;" : "=f"(r) : "f"(a));
    return r;
}

__global__ __launch_bounds__(256) void sobel_cat_kernel(
    const float* __restrict__ x, float* __restrict__ out)
{
    const int warp = blockIdx.x * (blockDim.x >> 5) + (threadIdx.x >> 5);
    const int lane = threadIdx.x & 31;
    const int h    = warp & (H - 1);
    const int bd   = warp >> 8;          // b*D + d
    const int w0   = lane << 2;          // chunk0: px w0..w0+3, chunk1: +128

    const float* base = x + ((size_t)bd * H + h) * W + w0;
    const bool ht = (h > 0), hb = (h < H - 1);

    float4 z = make_float4(0.f, 0.f, 0.f, 0.f);
    float4 t0 = z, t1 = z, b0 = z, b1 = z;
    float4 m0 = __ldg((const float4*)base);
    float4 m1 = __ldg((const float4*)(base + 128));
    if (ht) { t0 = __ldg((const float4*)(base - W));
              t1 = __ldg((const float4*)(base + 128 - W)); }
    if (hb) { b0 = __ldg((const float4*)(base + W));
              b1 = __ldg((const float4*)(base + 128 + W)); }

    const unsigned full = 0xFFFFFFFFu;

    float t0l = __shfl_up_sync(full, t0.w, 1);
    float m0l = __shfl_up_sync(full, m0.w, 1);
    float b0l = __shfl_up_sync(full, b0.w, 1);
    float t0r = __shfl_down_sync(full, t0.x, 1);
    float m0r = __shfl_down_sync(full, m0.x, 1);
    float b0r = __shfl_down_sync(full, b0.x, 1);
    float t1x0 = __shfl_sync(full, t1.x, 0);
    float m1x0 = __shfl_sync(full, m1.x, 0);
    float b1x0 = __shfl_sync(full, b1.x, 0);
    if (lane == 0)  { t0l = 0.f; m0l = 0.f; b0l = 0.f; }
    if (lane == 31) { t0r = t1x0; m0r = m1x0; b0r = b1x0; }

    float t1l = __shfl_up_sync(full, t1.w, 1);
    float m1l = __shfl_up_sync(full, m1.w, 1);
    float b1l = __shfl_up_sync(full, b1.w, 1);
    float t1r = __shfl_down_sync(full, t1.x, 1);
    float m1r = __shfl_down_sync(full, m1.x, 1);
    float b1r = __shfl_down_sync(full, b1.x, 1);
    float t0w31 = __shfl_sync(full, t0.w, 31);
    float m0w31 = __shfl_sync(full, m0.w, 31);
    float b0w31 = __shfl_sync(full, b0.w, 31);
    if (lane == 0)  { t1l = t0w31; m1l = m0w31; b1l = b0w31; }
    if (lane == 31) { t1r = 0.f; m1r = 0.f; b1r = 0.f; }

    float4 s0, s1;
    {
        float T[6] = { t0l, t0.x, t0.y, t0.z, t0.w, t0r };
        float M[6] = { m0l, m0.x, m0.y, m0.z, m0.w, m0r };
        float Bt[6] = { b0l, b0.x, b0.y, b0.z, b0.w, b0r };
        float* s = reinterpret_cast<float*>(&s0);
#pragma unroll
        for (int i = 0; i < 4; i++) {
            float gx = (T[i+2] - T[i]) + 2.f*(M[i+2] - M[i]) + (Bt[i+2] - Bt[i]);
            float gy = (Bt[i] - T[i]) + 2.f*(Bt[i+1] - T[i+1]) + (Bt[i+2] - T[i+2]);
            s[i] = fsqrt_approx(gx*gx + gy*gy);
        }
    }
    {
        float T[6] = { t1l, t1.x, t1.y, t1.z, t1.w, t1r };
        float M[6] = { m1l, m1.x, m1.y, m1.z, m1.w, m1r };
        float Bt[6] = { b1l, b1.x, b1.y, b1.z, b1.w, b1r };
        float* s = reinterpret_cast<float*>(&s1);
#pragma unroll
        for (int i = 0; i < 4; i++) {
            float gx = (T[i+2] - T[i]) + 2.f*(M[i+2] - M[i]) + (Bt[i+2] - Bt[i]);
            float gy = (Bt[i] - T[i]) + 2.f*(Bt[i+1] - T[i+1]) + (Bt[i+2] - T[i+2]);
            s[i] = fsqrt_approx(gx*gx + gy*gy);
        }
    }

    const int b = bd >> 6;           // bd / D
    const int d = bd & (DD - 1);     // bd % D
    const size_t cs = (size_t)DD * H * W;  // channel stride (elems)
    float* obase = out + (((size_t)b * 16 * DD + d) * H + h) * W + w0;

#pragma unroll
    for (int c = 0; c < 8; c++) {
        float* p = obase + (size_t)(2 * c) * cs;   // sobel channel
        *(float4*)(p)         = s0;
        *(float4*)(p + 128)   = s1;
        float* q = p + cs;                         // copy channel
        *(float4*)(q)         = m0;
        *(float4*)(q + 128)   = m1;
    }
}

extern "C" void kernel_launch(void* const* d_in, const int* in_sizes, int n_in,
                              void* d_out, int out_size)
{
    const float* x = (const float*)d_in[0];
    float* out = (float*)d_out;

    // one warp per row: NB*DD*H = 32768 warps, 8 warps per block
    const int total_warps = NB * DD * H;
    const int threads = 256;
    const int blocks = total_warps * 32 / threads;   // 4096
    sobel_cat_kernel<<<blocks, threads>>>(x, out);
}

// round 9
// speedup vs baseline: 1.0553x; 1.0432x over previous
#include <cuda_runtime.h>

// x:   [B=2, 1, D=64, H=256, W=256] fp32
// out: [B=2, 16, D=64, H=256, W=256] fp32
//   even channel -> per-slice 2D sobel magnitude, odd channel -> x
//
// FINAL (R4 config — empirical best over 8 rounds; kernel is HBM-write
// ceiling bound at ~5.85 TB/s, no SM-side unit above 80%):
// One warp = one full 256-px row. Lane l owns two float4 chunks (w=4l,
// w=4l+128). All halos via warp shuffle (zero scalar edge loads).
// sqrt.approx (single MUFU op). 32 fully-coalesced streaming STG.128/thread.

#define W 256
#define H 256
#define DD 64
#define NB 2

__device__ __forceinline__ float fsqrt_approx(float a) {
    float r;
    asm("sqrt.approx.f32 %0, %1;" : "=f"(r) : "f"(a));
    return r;
}

__global__ __launch_bounds__(256) void sobel_cat_kernel(
    const float* __restrict__ x, float* __restrict__ out)
{
    const int warp = blockIdx.x * (blockDim.x >> 5) + (threadIdx.x >> 5);
    const int lane = threadIdx.x & 31;
    const int h    = warp & (H - 1);
    const int bd   = warp >> 8;          // b*D + d
    const int w0   = lane << 2;          // chunk0: px w0..w0+3, chunk1: +128

    const float* base = x + ((size_t)bd * H + h) * W + w0;
    const bool ht = (h > 0), hb = (h < H - 1);

    float4 z = make_float4(0.f, 0.f, 0.f, 0.f);
    float4 t0 = z, t1 = z, b0 = z, b1 = z;
    float4 m0 = __ldg((const float4*)base);
    float4 m1 = __ldg((const float4*)(base + 128));
    if (ht) { t0 = __ldg((const float4*)(base - W));
              t1 = __ldg((const float4*)(base + 128 - W)); }
    if (hb) { b0 = __ldg((const float4*)(base + W));
              b1 = __ldg((const float4*)(base + 128 + W)); }

    const unsigned full = 0xFFFFFFFFu;

    // chunk0 halos: left = lane-1 c0.w (lane0 -> 0 pad),
    //               right = lane+1 c0.x (lane31 -> c1.x of lane0)
    float t0l = __shfl_up_sync(full, t0.w, 1);
    float m0l = __shfl_up_sync(full, m0.w, 1);
    float b0l = __shfl_up_sync(full, b0.w, 1);
    float t0r = __shfl_down_sync(full, t0.x, 1);
    float m0r = __shfl_down_sync(full, m0.x, 1);
    float b0r = __shfl_down_sync(full, b0.x, 1);
    float t1x0 = __shfl_sync(full, t1.x, 0);
    float m1x0 = __shfl_sync(full, m1.x, 0);
    float b1x0 = __shfl_sync(full, b1.x, 0);
    if (lane == 0)  { t0l = 0.f; m0l = 0.f; b0l = 0.f; }
    if (lane == 31) { t0r = t1x0; m0r = m1x0; b0r = b1x0; }

    // chunk1 halos: left = lane-1 c1.w (lane0 -> c0.w of lane31),
    //               right = lane+1 c1.x (lane31 -> 0 pad)
    float t1l = __shfl_up_sync(full, t1.w, 1);
    float m1l = __shfl_up_sync(full, m1.w, 1);
    float b1l = __shfl_up_sync(full, b1.w, 1);
    float t1r = __shfl_down_sync(full, t1.x, 1);
    float m1r = __shfl_down_sync(full, m1.x, 1);
    float b1r = __shfl_down_sync(full, b1.x, 1);
    float t0w31 = __shfl_sync(full, t0.w, 31);
    float m0w31 = __shfl_sync(full, m0.w, 31);
    float b0w31 = __shfl_sync(full, b0.w, 31);
    if (lane == 0)  { t1l = t0w31; m1l = m0w31; b1l = b0w31; }
    if (lane == 31) { t1r = 0.f; m1r = 0.f; b1r = 0.f; }

    float4 s0, s1;
    {
        float T[6] = { t0l, t0.x, t0.y, t0.z, t0.w, t0r };
        float M[6] = { m0l, m0.x, m0.y, m0.z, m0.w, m0r };
        float Bt[6] = { b0l, b0.x, b0.y, b0.z, b0.w, b0r };
        float* s = reinterpret_cast<float*>(&s0);
#pragma unroll
        for (int i = 0; i < 4; i++) {
            float gx = (T[i+2] - T[i]) + 2.f*(M[i+2] - M[i]) + (Bt[i+2] - Bt[i]);
            float gy = (Bt[i] - T[i]) + 2.f*(Bt[i+1] - T[i+1]) + (Bt[i+2] - T[i+2]);
            s[i] = fsqrt_approx(gx*gx + gy*gy);
        }
    }
    {
        float T[6] = { t1l, t1.x, t1.y, t1.z, t1.w, t1r };
        float M[6] = { m1l, m1.x, m1.y, m1.z, m1.w, m1r };
        float Bt[6] = { b1l, b1.x, b1.y, b1.z, b1.w, b1r };
        float* s = reinterpret_cast<float*>(&s1);
#pragma unroll
        for (int i = 0; i < 4; i++) {
            float gx = (T[i+2] - T[i]) + 2.f*(M[i+2] - M[i]) + (Bt[i+2] - Bt[i]);
            float gy = (Bt[i] - T[i]) + 2.f*(Bt[i+1] - T[i+1]) + (Bt[i+2] - T[i+2]);
            s[i] = fsqrt_approx(gx*gx + gy*gy);
        }
    }

    const int b = bd >> 6;           // bd / D
    const int d = bd & (DD - 1);     // bd % D
    const size_t cs = (size_t)DD * H * W;  // channel stride (elems)
    float* obase = out + (((size_t)b * 16 * DD + d) * H + h) * W + w0;

#pragma unroll
    for (int c = 0; c < 8; c++) {
        float* p = obase + (size_t)(2 * c) * cs;   // sobel channel
        __stcs((float4*)p,           s0);
        __stcs((float4*)(p + 128),   s1);
        float* q = p + cs;                         // copy channel
        __stcs((float4*)q,           m0);
        __stcs((float4*)(q + 128),   m1);
    }
}

extern "C" void kernel_launch(void* const* d_in, const int* in_sizes, int n_in,
                              void* d_out, int out_size)
{
    const float* x = (const float*)d_in[0];
    float* out = (float*)d_out;

    // one warp per row: NB*DD*H = 32768 warps, 8 warps per block
    const int total_warps = NB * DD * H;
    const int threads = 256;
    const int blocks = total_warps * 32 / threads;   // 4096
    sobel_cat_kernel<<<blocks, threads>>>(x, out);
}